// round 14
// baseline (speedup 1.0000x reference)
#include <cuda_runtime.h>
#include <cuda_bf16.h>
#include <cstdint>

// Problem constants
#define BSZ   2
#define CDIM  1024
#define CIDIM 512
#define NDIM  6272     // 32*14*14 = 49*128
#define TDIM  32

// bf16 scratch (allocation-free rule: __device__ globals)
__device__ __align__(256) __nv_bfloat16 g_xT[(size_t)BSZ * NDIM * CDIM];
__device__ __align__(256) __nv_bfloat16 g_Wk[CIDIM * CDIM];
__device__ __align__(256) __nv_bfloat16 g_Wq[CIDIM * CDIM];
__device__ __align__(256) __nv_bfloat16 g_Wv[CIDIM * CDIM];
__device__ __align__(256) __nv_bfloat16 g_Wo[CDIM * CIDIM];
__device__ __align__(256) __nv_bfloat16 g_Kt[(size_t)BSZ * NDIM * CIDIM];
__device__ __align__(256) __nv_bfloat16 g_Qt[(size_t)BSZ * NDIM * CIDIM];
__device__ __align__(256) __nv_bfloat16 g_Vt[(size_t)BSZ * NDIM * CIDIM];  // V^T [n,c]
__device__ __align__(256) __nv_bfloat16 g_V [(size_t)BSZ * CIDIM * NDIM]; // V [c,n]
__device__ __align__(256) __nv_bfloat16 g_Yt[(size_t)BSZ * NDIM * CIDIM];
__device__ __align__(256) __nv_bfloat16 g_Sb[(size_t)BSZ * NDIM * NDIM]; // bf16 scores
__device__ __align__(256) __nv_bfloat16 g_P [(size_t)BSZ * NDIM * NDIM]; // bf16 probs

// ---------------------------------------------------------------------------
__device__ __forceinline__ uint32_t smem_u32(const void* p) {
    uint32_t a;
    asm("{ .reg .u64 t; cvta.to.shared.u64 t, %1; cvt.u32.u64 %0, t; }"
        : "=r"(a) : "l"(p));
    return a;
}

#define LDSM4(rr, addr) \
    asm volatile("ldmatrix.sync.aligned.m8n8.x4.shared.b16 {%0,%1,%2,%3}, [%4];" \
        : "=r"((rr)[0]), "=r"((rr)[1]), "=r"((rr)[2]), "=r"((rr)[3]) : "r"(addr))

#define MMA(dd, aa, b0v, b1v) \
    asm volatile("mma.sync.aligned.m16n8k16.row.col.f32.bf16.bf16.f32 " \
        "{%0,%1,%2,%3}, {%4,%5,%6,%7}, {%8,%9}, {%0,%1,%2,%3};" \
        : "+f"((dd)[0]), "+f"((dd)[1]), "+f"((dd)[2]), "+f"((dd)[3]) \
        : "r"((aa)[0]), "r"((aa)[1]), "r"((aa)[2]), "r"((aa)[3]), \
          "r"(b0v), "r"(b1v))

#define CP16(dst, src) \
    asm volatile("cp.async.cg.shared.global [%0], [%1], 16;" :: "r"(dst), "l"(src))
#define CP_COMMIT() asm volatile("cp.async.commit_group;" ::: "memory")
#define CP_WAIT0()  asm volatile("cp.async.wait_group 0;" ::: "memory")

// SMEM: per stage 2 tiles (A, B), each 128 rows x 80B (64B data + 16 pad)
// K-chunk = 32 elements (64 bytes). 2 stages = 40 KB -> 3 CTAs/SM.
#define ROWB   80u
#define TILEB  (128u * ROWB)     // 10240
#define STAGEB (2u * TILEB)      // 20480
#define SMEMSZ (2u * STAGEB)     // 40960

__device__ __forceinline__ uint32_t cvt2(float a, float b) {
    __nv_bfloat16 ha = __float2bfloat16(a);
    __nv_bfloat16 hb = __float2bfloat16(b);
    return (uint32_t)__bfloat16_as_ushort(ha)
         | ((uint32_t)__bfloat16_as_ushort(hb) << 16);
}
__device__ __forceinline__ void unpack2(uint32_t u, float& a, float& b) {
    a = __bfloat162float(__ushort_as_bfloat16((unsigned short)(u & 0xffff)));
    b = __bfloat162float(__ushort_as_bfloat16((unsigned short)(u >> 16)));
}

// ---------------------------------------------------------------------------
// Pure-bf16 GEMM: acc[i,j] = sum_k A[i,k]*B[j,k]   (fp32 accumulate)
// A: M x K (K-major, ld=ldab), B: N' x K (K-major, ld=ldab)
// CTA tile 128x128, 128 threads, 4 warps (2x2), warp tile 64x64, K-chunk 32,
// 3 CTAs/SM (40 KB smem, <=168 regs).
// EPI: 0 = bf16 out, scale                (scores & alphaV; z = batch)
//      1 = TRIPLE bf16 out + bias[col]    (KQV proj; z = batch + 2*sel, sel 0..2)
//      4 = f32 out + bias[row] + resid    (out proj; z = batch)
// ---------------------------------------------------------------------------
template <int EPI>
__global__ __launch_bounds__(128, 3)
void tgemm(const __nv_bfloat16* __restrict__ Ab,
           const __nv_bfloat16* __restrict__ B0, const __nv_bfloat16* __restrict__ B1,
           const __nv_bfloat16* __restrict__ B2,
           float* __restrict__ Cf,
           __nv_bfloat16* __restrict__ C0, __nv_bfloat16* __restrict__ C1,
           __nv_bfloat16* __restrict__ C2,
           int Kd, int ldab, int ldc,
           size_t aStr, size_t bStr, size_t cStr,
           const float* __restrict__ bias0, const float* __restrict__ bias1,
           const float* __restrict__ bias2,
           const float* __restrict__ resid, size_t rStr, float scale)
{
    extern __shared__ __align__(128) char smem[];
    const int tid  = threadIdx.x;
    const int lane = tid & 31;
    const int wid  = tid >> 5;        // 0..3
    const int wm   = wid >> 1;        // 0..1
    const int wn   = wid & 1;         // 0..1

    const int batch = blockIdx.z & 1;
    const int sel   = blockIdx.z >> 1;

    const __nv_bfloat16* Ap = Ab + (size_t)batch * aStr;
    const __nv_bfloat16* Bp;
    if (EPI == 1) Bp = (sel == 0) ? B0 : (sel == 1) ? B1 : B2;
    else          Bp = B0;
    Bp += (size_t)batch * bStr;

    const int rowA = blockIdx.y * 128;
    const int rowB = blockIdx.x * 128;
    const uint32_t sb = smem_u32(smem);

    // ldmatrix base addresses
    const uint32_t aAddr = sb
        + (uint32_t)(wm * 64 + (lane & 15)) * ROWB + (uint32_t)(lane >> 4) * 16;
    const int bq = lane >> 3;
    const uint32_t bAddr = sb + TILEB
        + (uint32_t)(wn * 64 + (bq >> 1) * 8 + (lane & 7)) * ROWB
        + (uint32_t)(bq & 1) * 16;

    float d[4][8][4];
    #pragma unroll
    for (int i = 0; i < 4; i++)
        #pragma unroll
        for (int j = 0; j < 8; j++)
            #pragma unroll
            for (int q = 0; q < 4; q++) d[i][j][q] = 0.f;

    const int nk = Kd / 32;
    const int lrow = tid >> 2;        // 0..31
    const int lc8  = (tid & 3) * 8;   // 0,8,16,24

    auto LOAD = [&](int kc, int s) {
        const uint32_t so = sb + (uint32_t)s * STAGEB;
        const int k0 = kc * 32 + lc8;
        #pragma unroll
        for (int t = 0; t < 2; t++) {
            const __nv_bfloat16* src = t ? Bp : Ap;
            const int rb = t ? rowB : rowA;
            #pragma unroll
            for (int r = 0; r < 4; r++) {
                const int row = lrow + r * 32;
                const uint32_t dst = so + (uint32_t)t * TILEB
                                   + (uint32_t)row * ROWB + (uint32_t)(lc8 * 2);
                CP16(dst, src + (size_t)(rb + row) * ldab + k0);
            }
        }
        CP_COMMIT();
    };

    // B fragments resident (64 cols), A streamed per mi; 8 MMA per A-LDSM.
    auto COMPUTE = [&](int s) {
        const uint32_t so = (uint32_t)s * STAGEB;
        #pragma unroll
        for (int ks = 0; ks < 2; ks++) {
            const uint32_t ab = aAddr + so + ks * 32;
            const uint32_t bb = bAddr + so + ks * 32;
            uint32_t bh[4][4];
            #pragma unroll
            for (int np = 0; np < 4; np++)
                LDSM4(bh[np], bb + np * 16 * ROWB);
            #pragma unroll
            for (int mi = 0; mi < 4; mi++) {
                uint32_t ah[4];
                LDSM4(ah, ab + mi * 16 * ROWB);
                #pragma unroll
                for (int ni = 0; ni < 8; ni++) {
                    const int np = ni >> 1, h = (ni & 1) * 2;
                    MMA(d[mi][ni], ah, bh[np][h], bh[np][h + 1]);
                }
            }
        }
    };

    LOAD(0, 0);
    for (int c = 0; c < nk; c++) {
        const int s = c & 1;
        CP_WAIT0();
        __syncthreads();
        if (c + 1 < nk) LOAD(c + 1, s ^ 1);
        COMPUTE(s);
    }

    // ---- epilogue ----
    float* Cfp = nullptr;
    __nv_bfloat16* Cb = nullptr;
    if (EPI == 4) Cfp = Cf + (size_t)batch * cStr;
    if (EPI == 0) Cb = C0 + (size_t)batch * cStr;
    if (EPI == 1)
        Cb = ((sel == 0) ? C0 : (sel == 1) ? C1 : C2) + (size_t)batch * cStr;
    const float* bp = (EPI == 1)
        ? ((sel == 0) ? bias0 : (sel == 1) ? bias1 : bias2) : bias0;

    const int r0base = rowA + wm * 64;
    const int c0base = rowB + wn * 64;
    #pragma unroll
    for (int mi = 0; mi < 4; mi++) {
        const int row0 = r0base + mi * 16 + (lane >> 2);
        const int row1 = row0 + 8;
        float bi0 = 0.f, bi1 = 0.f;
        if (EPI == 4) { bi0 = bp[row0]; bi1 = bp[row1]; }
        #pragma unroll
        for (int ni = 0; ni < 8; ni++) {
            const int col = c0base + ni * 8 + (lane & 3) * 2;
            float v00 = d[mi][ni][0] * scale, v01 = d[mi][ni][1] * scale;
            float v10 = d[mi][ni][2] * scale, v11 = d[mi][ni][3] * scale;
            if (EPI == 1) {
                float b0 = bp[col], b1 = bp[col + 1];
                v00 += b0; v01 += b1; v10 += b0; v11 += b1;
            }
            if (EPI == 4) {
                v00 += bi0; v01 += bi0; v10 += bi1; v11 += bi1;
                const float* rb = resid + (size_t)batch * rStr;
                float2 q0 = *(const float2*)(rb + (size_t)row0 * ldc + col);
                float2 q1 = *(const float2*)(rb + (size_t)row1 * ldc + col);
                v00 += q0.x; v01 += q0.y; v10 += q1.x; v11 += q1.y;
            }
            if (EPI == 4) {
                *(float2*)(Cfp + (size_t)row0 * ldc + col) = make_float2(v00, v01);
                *(float2*)(Cfp + (size_t)row1 * ldc + col) = make_float2(v10, v11);
            } else {
                *(uint32_t*)(Cb + (size_t)row0 * ldc + col) = cvt2(v00, v01);
                *(uint32_t*)(Cb + (size_t)row1 * ldc + col) = cvt2(v10, v11);
            }
        }
    }
}

// ---------------------------------------------------------------------------
// 32x32 tiled transpose + convert: x (B,C,N) fp32 -> xT (B,N,C) bf16
// ---------------------------------------------------------------------------
__global__ __launch_bounds__(256)
void transpose_cvt(const float* __restrict__ src, __nv_bfloat16* __restrict__ dst)
{
    __shared__ float t[32][33];
    const float* s = src + (size_t)blockIdx.z * CDIM * NDIM;
    __nv_bfloat16* o = dst + (size_t)blockIdx.z * NDIM * CDIM;
    const int n0 = blockIdx.x * 32;
    const int c0 = blockIdx.y * 32;
    const int tx = threadIdx.x, ty = threadIdx.y;
    #pragma unroll
    for (int r = 0; r < 4; r++)
        t[ty + r * 8][tx] = s[(size_t)(c0 + ty + r * 8) * NDIM + n0 + tx];
    __syncthreads();
    #pragma unroll
    for (int r = 0; r < 4; r++)
        o[(size_t)(n0 + ty + r * 8) * CDIM + c0 + tx] =
            __float2bfloat16(t[tx][ty + r * 8]);
}

// 32x32 bf16 transpose: Vt (B,N,CI) -> V (B,CI,N)
__global__ __launch_bounds__(256)
void transpose_v(const __nv_bfloat16* __restrict__ s, __nv_bfloat16* __restrict__ d)
{
    __shared__ ushort t[32][33];
    const size_t bo = (size_t)blockIdx.z * NDIM * CIDIM;
    const int n0 = blockIdx.x * 32;
    const int c0 = blockIdx.y * 32;
    const int tx = threadIdx.x, ty = threadIdx.y;
    #pragma unroll
    for (int r = 0; r < 4; r++)
        t[ty + r * 8][tx] = __bfloat16_as_ushort(
            s[bo + (size_t)(n0 + ty + r * 8) * CIDIM + c0 + tx]);
    __syncthreads();
    #pragma unroll
    for (int r = 0; r < 4; r++)
        d[bo + (size_t)(c0 + ty + r * 8) * NDIM + n0 + tx] =
            __ushort_as_bfloat16(t[tx][ty + r * 8]);
}

// All 4 weight matrices fp32 -> bf16 in one launch (blockIdx.y selects matrix).
__global__ __launch_bounds__(256)
void cvt_weights(const float* __restrict__ s0, const float* __restrict__ s1,
                 const float* __restrict__ s2, const float* __restrict__ s3,
                 __nv_bfloat16* __restrict__ d0, __nv_bfloat16* __restrict__ d1,
                 __nv_bfloat16* __restrict__ d2, __nv_bfloat16* __restrict__ d3,
                 int n4)
{
    const int m = blockIdx.y;
    const float* src = (m == 0) ? s0 : (m == 1) ? s1 : (m == 2) ? s2 : s3;
    __nv_bfloat16* dst = (m == 0) ? d0 : (m == 1) ? d1 : (m == 2) ? d2 : d3;
    const int i = blockIdx.x * 256 + threadIdx.x;
    if (i >= n4) return;
    float4 v = ((const float4*)src)[i];
    ((uint2*)dst)[i] = make_uint2(cvt2(v.x, v.y), cvt2(v.z, v.w));
}

// ---------------------------------------------------------------------------
// Row softmax: bf16 scores in -> bf16 probabilities out, vectorized uint4
// (8 bf16 per ld/st). Row length 6272 = 784 uint4; 256 threads, 4 iters.
// ---------------------------------------------------------------------------
#define SM_V4 4   // uint4 per thread (4*256 = 1024 >= 784)
__global__ __launch_bounds__(256)
void softmax_cvt(const __nv_bfloat16* __restrict__ S, __nv_bfloat16* __restrict__ P,
                 int n)
{
    const uint4* row = (const uint4*)(S + (size_t)blockIdx.x * n);
    uint4* pr = (uint4*)(P + (size_t)blockIdx.x * n);
    const int n4 = n / 8;                 // 784
    const int t = threadIdx.x;
    __shared__ float red[256];

    float vals[SM_V4 * 8];
    float mx = -3.402823466e38f;
    #pragma unroll
    for (int v = 0; v < SM_V4; v++) {
        const int j = v * 256 + t;
        if (j < n4) {
            uint4 u = row[j];
            float* p = vals + v * 8;
            unpack2(u.x, p[0], p[1]); unpack2(u.y, p[2], p[3]);
            unpack2(u.z, p[4], p[5]); unpack2(u.w, p[6], p[7]);
            #pragma unroll
            for (int e = 0; e < 8; e++) mx = fmaxf(mx, p[e]);
        }
    }
    red[t] = mx; __syncthreads();
    for (int s = 128; s > 0; s >>= 1) {
        if (t < s) red[t] = fmaxf(red[t], red[t + s]);
        __syncthreads();
    }
    mx = red[0];
    __syncthreads();

    float sum = 0.f;
    #pragma unroll
    for (int v = 0; v < SM_V4; v++) {
        const int j = v * 256 + t;
        if (j < n4) {
            float* p = vals + v * 8;
            #pragma unroll
            for (int e = 0; e < 8; e++) { p[e] = __expf(p[e] - mx); sum += p[e]; }
        }
    }
    red[t] = sum; __syncthreads();
    for (int s = 128; s > 0; s >>= 1) {
        if (t < s) red[t] += red[t + s];
        __syncthreads();
    }
    const float inv = 1.f / red[0];

    #pragma unroll
    for (int v = 0; v < SM_V4; v++) {
        const int j = v * 256 + t;
        if (j < n4) {
            float* p = vals + v * 8;
            uint4 u;
            u.x = cvt2(p[0] * inv, p[1] * inv);
            u.y = cvt2(p[2] * inv, p[3] * inv);
            u.z = cvt2(p[4] * inv, p[5] * inv);
            u.w = cvt2(p[6] * inv, p[7] * inv);
            pr[j] = u;
        }
    }
}

// ---------------------------------------------------------------------------
extern "C" void kernel_launch(void* const* d_in, const int* in_sizes, int n_in,
                              void* d_out, int out_size)
{
    const float* x   = (const float*)d_in[0];   // (B, C, N)
    const float* Wkf = (const float*)d_in[1];   // (CI, C)
    const float* bk  = (const float*)d_in[2];
    const float* Wqf = (const float*)d_in[3];
    const float* bq  = (const float*)d_in[4];
    const float* Wvf = (const float*)d_in[5];
    const float* bv  = (const float*)d_in[6];
    const float* Wof = (const float*)d_in[7];   // (C, CI)
    const float* bo  = (const float*)d_in[8];
    float* out = (float*)d_out;                 // (B, C, N)

    __nv_bfloat16 *xT, *Wk, *Wq, *Wv, *Wo, *Kt, *Qt, *Vt, *V, *Yt, *Sb, *P;
    cudaGetSymbolAddress((void**)&xT, g_xT);
    cudaGetSymbolAddress((void**)&Wk, g_Wk);
    cudaGetSymbolAddress((void**)&Wq, g_Wq);
    cudaGetSymbolAddress((void**)&Wv, g_Wv);
    cudaGetSymbolAddress((void**)&Wo, g_Wo);
    cudaGetSymbolAddress((void**)&Kt, g_Kt);
    cudaGetSymbolAddress((void**)&Qt, g_Qt);
    cudaGetSymbolAddress((void**)&Vt, g_Vt);
    cudaGetSymbolAddress((void**)&V,  g_V);
    cudaGetSymbolAddress((void**)&Yt, g_Yt);
    cudaGetSymbolAddress((void**)&Sb, g_Sb);
    cudaGetSymbolAddress((void**)&P,  g_P);

    cudaFuncSetAttribute(tgemm<0>, cudaFuncAttributeMaxDynamicSharedMemorySize, SMEMSZ);
    cudaFuncSetAttribute(tgemm<1>, cudaFuncAttributeMaxDynamicSharedMemorySize, SMEMSZ);
    cudaFuncSetAttribute(tgemm<4>, cudaFuncAttributeMaxDynamicSharedMemorySize, SMEMSZ);

    const size_t pstr = (size_t)NDIM * CIDIM;   // Kt/Qt/Vt/Yt batch stride
    const size_t vstr = (size_t)CIDIM * NDIM;   // V batch stride
    const size_t xstr = (size_t)CDIM * NDIM;    // x/out batch stride
    const size_t tstr = (size_t)NDIM * CDIM;    // xT batch stride
    const size_t sstr = (size_t)NDIM * NDIM;    // Sb/P batch stride

    const int w4 = (CIDIM * CDIM) / 4;

    // 0) converts (single launch for weights, one for xT)
    transpose_cvt<<<dim3(NDIM / 32, CDIM / 32, BSZ), dim3(32, 8)>>>(x, xT);
    cvt_weights<<<dim3((w4 + 255) / 256, 4), 256>>>(Wkf, Wqf, Wvf, Wof,
                                                    Wk, Wq, Wv, Wo, w4);

    // 1) K, Q, V projections merged (TRIPLE): {Kt,Qt,Vt}[n,d] = xT[n,:]·W[d,:] + b[d]
    tgemm<1><<<dim3(CIDIM / 128, NDIM / 128, 3 * BSZ), 128, SMEMSZ>>>(
        xT, Wk, Wq, Wv,
        nullptr, Kt, Qt, Vt,
        CDIM, CDIM, CIDIM, tstr, 0, pstr, bk, bq, bv, nullptr, 0, 1.0f);

    // 1b) V[c,n] = transpose(Vt)
    transpose_v<<<dim3(NDIM / 32, CIDIM / 32, BSZ), dim3(32, 8)>>>(Vt, V);

    // 2) Sb[i,j] = bf16( (1/T) Kt[i,:]·Qt[j,:] )
    tgemm<0><<<dim3(NDIM / 128, NDIM / 128, BSZ), 128, SMEMSZ>>>(
        Kt, Qt, nullptr, nullptr,
        nullptr, Sb, nullptr, nullptr,
        CIDIM, CIDIM, NDIM, pstr, pstr, sstr, nullptr, nullptr, nullptr,
        nullptr, 0, 1.0f / (float)TDIM);

    // 3) softmax -> P bf16
    softmax_cvt<<<BSZ * NDIM, 256>>>(Sb, P, NDIM);

    // 4) Yt[i,c] = bf16( P[i,:]·V[c,:] )  (full-K; 392 CTAs < 444 slots at 3/SM)
    tgemm<0><<<dim3(CIDIM / 128, NDIM / 128, BSZ), 128, SMEMSZ>>>(
        P, V, nullptr, nullptr,
        nullptr, Yt, nullptr, nullptr,
        NDIM, NDIM, CIDIM, sstr, vstr, pstr, nullptr, nullptr, nullptr,
        nullptr, 0, 1.0f);

    // 5) out[c,n] = Wo[c,:]·Yt[n,:] + bo[c] + x[c,n]  (fp32 out)
    tgemm<4><<<dim3(NDIM / 128, CDIM / 128, BSZ), 128, SMEMSZ>>>(
        Wo, Yt, nullptr, nullptr,
        out, nullptr, nullptr, nullptr,
        CIDIM, CIDIM, NDIM, 0, pstr, xstr, bo, nullptr, nullptr, x, xstr, 1.0f);
}

// round 15
// speedup vs baseline: 1.0764x; 1.0764x over previous
#include <cuda_runtime.h>
#include <cuda_bf16.h>
#include <cstdint>

// Problem constants
#define BSZ   2
#define CDIM  1024
#define CIDIM 512
#define NDIM  6272     // 32*14*14 = 49*128
#define NHALF 3136     // NDIM/2 (split-K for alpha*V)
#define TDIM  32

// bf16 scratch (allocation-free rule: __device__ globals)
__device__ __align__(256) __nv_bfloat16 g_xT[(size_t)BSZ * NDIM * CDIM];
__device__ __align__(256) __nv_bfloat16 g_Wk[CIDIM * CDIM];
__device__ __align__(256) __nv_bfloat16 g_Wq[CIDIM * CDIM];
__device__ __align__(256) __nv_bfloat16 g_Wv[CIDIM * CDIM];
__device__ __align__(256) __nv_bfloat16 g_Wo[CDIM * CIDIM];
__device__ __align__(256) __nv_bfloat16 g_Kt[(size_t)BSZ * NDIM * CIDIM];
__device__ __align__(256) __nv_bfloat16 g_Qt[(size_t)BSZ * NDIM * CIDIM];
__device__ __align__(256) __nv_bfloat16 g_Vt[(size_t)BSZ * NDIM * CIDIM];  // V^T [n,c]
__device__ __align__(256) __nv_bfloat16 g_V [(size_t)BSZ * CIDIM * NDIM]; // V [c,n]
__device__ __align__(256) __nv_bfloat16 g_Yt[(size_t)BSZ * NDIM * CIDIM];
__device__ __align__(256) __nv_bfloat16 g_Sb[(size_t)BSZ * NDIM * NDIM]; // bf16 scores
__device__ __align__(256) __nv_bfloat16 g_P [(size_t)BSZ * NDIM * NDIM]; // bf16 probs
__device__ __align__(256) float         g_Yp[(size_t)2 * BSZ * NDIM * CIDIM]; // split-K partials

// ---------------------------------------------------------------------------
__device__ __forceinline__ uint32_t smem_u32(const void* p) {
    uint32_t a;
    asm("{ .reg .u64 t; cvta.to.shared.u64 t, %1; cvt.u32.u64 %0, t; }"
        : "=r"(a) : "l"(p));
    return a;
}

#define LDSM4(rr, addr) \
    asm volatile("ldmatrix.sync.aligned.m8n8.x4.shared.b16 {%0,%1,%2,%3}, [%4];" \
        : "=r"((rr)[0]), "=r"((rr)[1]), "=r"((rr)[2]), "=r"((rr)[3]) : "r"(addr))

#define MMA(dd, aa, b0v, b1v) \
    asm volatile("mma.sync.aligned.m16n8k16.row.col.f32.bf16.bf16.f32 " \
        "{%0,%1,%2,%3}, {%4,%5,%6,%7}, {%8,%9}, {%0,%1,%2,%3};" \
        : "+f"((dd)[0]), "+f"((dd)[1]), "+f"((dd)[2]), "+f"((dd)[3]) \
        : "r"((aa)[0]), "r"((aa)[1]), "r"((aa)[2]), "r"((aa)[3]), \
          "r"(b0v), "r"(b1v))

#define CP16(dst, src) \
    asm volatile("cp.async.cg.shared.global [%0], [%1], 16;" :: "r"(dst), "l"(src))
#define CP_COMMIT() asm volatile("cp.async.commit_group;" ::: "memory")
#define CP_WAIT0()  asm volatile("cp.async.wait_group 0;" ::: "memory")

// SMEM: per stage 2 tiles (A, B), each 128 rows x 144B (128B data + 16 pad)
// K-chunk = 64 elements (128 bytes).
#define ROWB   144u
#define TILEB  (128u * ROWB)     // 18432
#define STAGEB (2u * TILEB)      // 36864
#define SMEMSZ (2u * STAGEB)     // 73728

__device__ __forceinline__ uint32_t cvt2(float a, float b) {
    __nv_bfloat16 ha = __float2bfloat16(a);
    __nv_bfloat16 hb = __float2bfloat16(b);
    return (uint32_t)__bfloat16_as_ushort(ha)
         | ((uint32_t)__bfloat16_as_ushort(hb) << 16);
}
__device__ __forceinline__ void unpack2(uint32_t u, float& a, float& b) {
    a = __bfloat162float(__ushort_as_bfloat16((unsigned short)(u & 0xffff)));
    b = __bfloat162float(__ushort_as_bfloat16((unsigned short)(u >> 16)));
}

// ---------------------------------------------------------------------------
// Pure-bf16 GEMM: acc[i,j] = sum_k A[i,k]*B[j,k]   (fp32 accumulate)
// A: M x K (K-major, ld=ldab), B: N' x K (K-major, ld=ldab)
// CTA tile 128x128, 128 threads, 4 warps (2x2), warp tile 64x64, K-chunk 64.
// EPI: 0 = bf16 out, scale                (scores; z = batch)
//      1 = TRIPLE bf16 out + bias[col]    (KQV proj; z = batch + 2*sel, sel 0..2)
//      4 = f32 out + bias[row] + resid    (out proj; z = batch)
//      5 = split-K f32 partial out        (alphaV; z = batch + 2*kh, kh 0..1)
// ---------------------------------------------------------------------------
template <int EPI>
__global__ __launch_bounds__(128, 2)
void tgemm(const __nv_bfloat16* __restrict__ Ab,
           const __nv_bfloat16* __restrict__ B0, const __nv_bfloat16* __restrict__ B1,
           const __nv_bfloat16* __restrict__ B2,
           float* __restrict__ Cf,
           __nv_bfloat16* __restrict__ C0, __nv_bfloat16* __restrict__ C1,
           __nv_bfloat16* __restrict__ C2,
           int Kd, int ldab, int ldc,
           size_t aStr, size_t bStr, size_t cStr, size_t khStr,
           const float* __restrict__ bias0, const float* __restrict__ bias1,
           const float* __restrict__ bias2,
           const float* __restrict__ resid, size_t rStr, float scale)
{
    extern __shared__ __align__(128) char smem[];
    const int tid  = threadIdx.x;
    const int lane = tid & 31;
    const int wid  = tid >> 5;        // 0..3
    const int wm   = wid >> 1;        // 0..1
    const int wn   = wid & 1;         // 0..1

    const int batch = blockIdx.z & 1;
    const int sel   = blockIdx.z >> 1;

    const __nv_bfloat16* Ap = Ab + (size_t)batch * aStr;
    const __nv_bfloat16* Bp;
    if (EPI == 1) Bp = (sel == 0) ? B0 : (sel == 1) ? B1 : B2;
    else          Bp = B0;
    Bp += (size_t)batch * bStr;
    if (EPI == 5) {
        const int koff = sel * NHALF;
        Ap += koff; Bp += koff;
    }

    const int rowA = blockIdx.y * 128;
    const int rowB = blockIdx.x * 128;
    const uint32_t sb = smem_u32(smem);

    // ldmatrix base addresses
    const uint32_t aAddr = sb
        + (uint32_t)(wm * 64 + (lane & 15)) * ROWB + (uint32_t)(lane >> 4) * 16;
    const int bq = lane >> 3;
    const uint32_t bAddr = sb + TILEB
        + (uint32_t)(wn * 64 + (bq >> 1) * 8 + (lane & 7)) * ROWB
        + (uint32_t)(bq & 1) * 16;

    float d[4][8][4];
    #pragma unroll
    for (int i = 0; i < 4; i++)
        #pragma unroll
        for (int j = 0; j < 8; j++)
            #pragma unroll
            for (int q = 0; q < 4; q++) d[i][j][q] = 0.f;

    const int nk = Kd / 64;
    const int lrow = tid >> 3;        // 0..15
    const int lc8  = (tid & 7) * 8;   // 0..56 (elements; x2 = byte offset)

    auto LOAD = [&](int kc, int s) {
        const uint32_t so = sb + (uint32_t)s * STAGEB;
        const int k0 = kc * 64 + lc8;
        #pragma unroll
        for (int t = 0; t < 2; t++) {
            const __nv_bfloat16* src = t ? Bp : Ap;
            const int rb = t ? rowB : rowA;
            #pragma unroll
            for (int r = 0; r < 8; r++) {
                const int row = lrow + r * 16;
                const uint32_t dst = so + (uint32_t)t * TILEB
                                   + (uint32_t)row * ROWB + (uint32_t)(lc8 * 2);
                CP16(dst, src + (size_t)(rb + row) * ldab + k0);
            }
        }
        CP_COMMIT();
    };

    // B fragments resident (64 cols), A streamed per mi; 8 MMA per A-LDSM.
    auto COMPUTE = [&](int s) {
        const uint32_t so = (uint32_t)s * STAGEB;
        #pragma unroll
        for (int ks = 0; ks < 4; ks++) {
            const uint32_t ab = aAddr + so + ks * 32;
            const uint32_t bb = bAddr + so + ks * 32;
            uint32_t bh[4][4];
            #pragma unroll
            for (int np = 0; np < 4; np++)
                LDSM4(bh[np], bb + np * 16 * ROWB);
            #pragma unroll
            for (int mi = 0; mi < 4; mi++) {
                uint32_t ah[4];
                LDSM4(ah, ab + mi * 16 * ROWB);
                #pragma unroll
                for (int ni = 0; ni < 8; ni++) {
                    const int np = ni >> 1, h = (ni & 1) * 2;
                    MMA(d[mi][ni], ah, bh[np][h], bh[np][h + 1]);
                }
            }
        }
    };

    LOAD(0, 0);
    for (int c = 0; c < nk; c++) {
        const int s = c & 1;
        CP_WAIT0();
        __syncthreads();
        if (c + 1 < nk) LOAD(c + 1, s ^ 1);
        COMPUTE(s);
    }

    // ---- epilogue ----
    float* Cfp = nullptr;
    __nv_bfloat16* Cb = nullptr;
    if (EPI == 4) Cfp = Cf + (size_t)batch * cStr;
    if (EPI == 5) Cfp = Cf + (size_t)batch * cStr + (size_t)sel * khStr;
    if (EPI == 0) Cb = C0 + (size_t)batch * cStr;
    if (EPI == 1)
        Cb = ((sel == 0) ? C0 : (sel == 1) ? C1 : C2) + (size_t)batch * cStr;
    const float* bp = (EPI == 1)
        ? ((sel == 0) ? bias0 : (sel == 1) ? bias1 : bias2) : bias0;

    const int r0base = rowA + wm * 64;
    const int c0base = rowB + wn * 64;
    #pragma unroll
    for (int mi = 0; mi < 4; mi++) {
        const int row0 = r0base + mi * 16 + (lane >> 2);
        const int row1 = row0 + 8;
        float bi0 = 0.f, bi1 = 0.f;
        if (EPI == 4) { bi0 = bp[row0]; bi1 = bp[row1]; }
        #pragma unroll
        for (int ni = 0; ni < 8; ni++) {
            const int col = c0base + ni * 8 + (lane & 3) * 2;
            float v00 = d[mi][ni][0] * scale, v01 = d[mi][ni][1] * scale;
            float v10 = d[mi][ni][2] * scale, v11 = d[mi][ni][3] * scale;
            if (EPI == 1) {
                float b0 = bp[col], b1 = bp[col + 1];
                v00 += b0; v01 += b1; v10 += b0; v11 += b1;
            }
            if (EPI == 4) {
                v00 += bi0; v01 += bi0; v10 += bi1; v11 += bi1;
                const float* rb = resid + (size_t)batch * rStr;
                float2 q0 = *(const float2*)(rb + (size_t)row0 * ldc + col);
                float2 q1 = *(const float2*)(rb + (size_t)row1 * ldc + col);
                v00 += q0.x; v01 += q0.y; v10 += q1.x; v11 += q1.y;
            }
            if (EPI == 4 || EPI == 5) {
                *(float2*)(Cfp + (size_t)row0 * ldc + col) = make_float2(v00, v01);
                *(float2*)(Cfp + (size_t)row1 * ldc + col) = make_float2(v10, v11);
            } else {
                *(uint32_t*)(Cb + (size_t)row0 * ldc + col) = cvt2(v00, v01);
                *(uint32_t*)(Cb + (size_t)row1 * ldc + col) = cvt2(v10, v11);
            }
        }
    }
}

// ---------------------------------------------------------------------------
// 32x32 tiled transpose + convert: x (B,C,N) fp32 -> xT (B,N,C) bf16
// ---------------------------------------------------------------------------
__global__ __launch_bounds__(256)
void transpose_cvt(const float* __restrict__ src, __nv_bfloat16* __restrict__ dst)
{
    __shared__ float t[32][33];
    const float* s = src + (size_t)blockIdx.z * CDIM * NDIM;
    __nv_bfloat16* o = dst + (size_t)blockIdx.z * NDIM * CDIM;
    const int n0 = blockIdx.x * 32;
    const int c0 = blockIdx.y * 32;
    const int tx = threadIdx.x, ty = threadIdx.y;
    #pragma unroll
    for (int r = 0; r < 4; r++)
        t[ty + r * 8][tx] = s[(size_t)(c0 + ty + r * 8) * NDIM + n0 + tx];
    __syncthreads();
    #pragma unroll
    for (int r = 0; r < 4; r++)
        o[(size_t)(n0 + ty + r * 8) * CDIM + c0 + tx] =
            __float2bfloat16(t[tx][ty + r * 8]);
}

// 32x32 bf16 transpose: Vt (B,N,CI) -> V (B,CI,N)
__global__ __launch_bounds__(256)
void transpose_v(const __nv_bfloat16* __restrict__ s, __nv_bfloat16* __restrict__ d)
{
    __shared__ ushort t[32][33];
    const size_t bo = (size_t)blockIdx.z * NDIM * CIDIM;
    const int n0 = blockIdx.x * 32;
    const int c0 = blockIdx.y * 32;
    const int tx = threadIdx.x, ty = threadIdx.y;
    #pragma unroll
    for (int r = 0; r < 4; r++)
        t[ty + r * 8][tx] = __bfloat16_as_ushort(
            s[bo + (size_t)(n0 + ty + r * 8) * CIDIM + c0 + tx]);
    __syncthreads();
    #pragma unroll
    for (int r = 0; r < 4; r++)
        d[bo + (size_t)(c0 + ty + r * 8) * NDIM + n0 + tx] =
            __ushort_as_bfloat16(t[tx][ty + r * 8]);
}

// All 4 weight matrices fp32 -> bf16 in one launch (blockIdx.y selects matrix).
__global__ __launch_bounds__(256)
void cvt_weights(const float* __restrict__ s0, const float* __restrict__ s1,
                 const float* __restrict__ s2, const float* __restrict__ s3,
                 __nv_bfloat16* __restrict__ d0, __nv_bfloat16* __restrict__ d1,
                 __nv_bfloat16* __restrict__ d2, __nv_bfloat16* __restrict__ d3,
                 int n4)
{
    const int m = blockIdx.y;
    const float* src = (m == 0) ? s0 : (m == 1) ? s1 : (m == 2) ? s2 : s3;
    __nv_bfloat16* dst = (m == 0) ? d0 : (m == 1) ? d1 : (m == 2) ? d2 : d3;
    const int i = blockIdx.x * 256 + threadIdx.x;
    if (i >= n4) return;
    float4 v = ((const float4*)src)[i];
    ((uint2*)dst)[i] = make_uint2(cvt2(v.x, v.y), cvt2(v.z, v.w));
}

// Combine split-K partials (y0 + y1) -> bf16
__global__ __launch_bounds__(256)
void combine_cvt(const float* __restrict__ y0, const float* __restrict__ y1,
                 __nv_bfloat16* __restrict__ dst, int n4)
{
    const int i = blockIdx.x * 256 + threadIdx.x;
    if (i >= n4) return;
    float4 a = ((const float4*)y0)[i];
    float4 b = ((const float4*)y1)[i];
    ((uint2*)dst)[i] = make_uint2(cvt2(a.x + b.x, a.y + b.y),
                                  cvt2(a.z + b.z, a.w + b.w));
}

// ---------------------------------------------------------------------------
// Row softmax: bf16 scores in -> bf16 probabilities out, vectorized uint4
// (8 bf16 per ld/st). Row length 6272 = 784 uint4; 256 threads, 4 iters.
// ---------------------------------------------------------------------------
#define SM_V4 4   // uint4 per thread (4*256 = 1024 >= 784)
__global__ __launch_bounds__(256)
void softmax_cvt(const __nv_bfloat16* __restrict__ S, __nv_bfloat16* __restrict__ P,
                 int n)
{
    const uint4* row = (const uint4*)(S + (size_t)blockIdx.x * n);
    uint4* pr = (uint4*)(P + (size_t)blockIdx.x * n);
    const int n4 = n / 8;                 // 784
    const int t = threadIdx.x;
    __shared__ float red[256];

    float vals[SM_V4 * 8];
    float mx = -3.402823466e38f;
    #pragma unroll
    for (int v = 0; v < SM_V4; v++) {
        const int j = v * 256 + t;
        if (j < n4) {
            uint4 u = row[j];
            float* p = vals + v * 8;
            unpack2(u.x, p[0], p[1]); unpack2(u.y, p[2], p[3]);
            unpack2(u.z, p[4], p[5]); unpack2(u.w, p[6], p[7]);
            #pragma unroll
            for (int e = 0; e < 8; e++) mx = fmaxf(mx, p[e]);
        }
    }
    red[t] = mx; __syncthreads();
    for (int s = 128; s > 0; s >>= 1) {
        if (t < s) red[t] = fmaxf(red[t], red[t + s]);
        __syncthreads();
    }
    mx = red[0];
    __syncthreads();

    float sum = 0.f;
    #pragma unroll
    for (int v = 0; v < SM_V4; v++) {
        const int j = v * 256 + t;
        if (j < n4) {
            float* p = vals + v * 8;
            #pragma unroll
            for (int e = 0; e < 8; e++) { p[e] = __expf(p[e] - mx); sum += p[e]; }
        }
    }
    red[t] = sum; __syncthreads();
    for (int s = 128; s > 0; s >>= 1) {
        if (t < s) red[t] += red[t + s];
        __syncthreads();
    }
    const float inv = 1.f / red[0];

    #pragma unroll
    for (int v = 0; v < SM_V4; v++) {
        const int j = v * 256 + t;
        if (j < n4) {
            float* p = vals + v * 8;
            uint4 u;
            u.x = cvt2(p[0] * inv, p[1] * inv);
            u.y = cvt2(p[2] * inv, p[3] * inv);
            u.z = cvt2(p[4] * inv, p[5] * inv);
            u.w = cvt2(p[6] * inv, p[7] * inv);
            pr[j] = u;
        }
    }
}

// ---------------------------------------------------------------------------
extern "C" void kernel_launch(void* const* d_in, const int* in_sizes, int n_in,
                              void* d_out, int out_size)
{
    const float* x   = (const float*)d_in[0];   // (B, C, N)
    const float* Wkf = (const float*)d_in[1];   // (CI, C)
    const float* bk  = (const float*)d_in[2];
    const float* Wqf = (const float*)d_in[3];
    const float* bq  = (const float*)d_in[4];
    const float* Wvf = (const float*)d_in[5];
    const float* bv  = (const float*)d_in[6];
    const float* Wof = (const float*)d_in[7];   // (C, CI)
    const float* bo  = (const float*)d_in[8];
    float* out = (float*)d_out;                 // (B, C, N)

    __nv_bfloat16 *xT, *Wk, *Wq, *Wv, *Wo, *Kt, *Qt, *Vt, *V, *Yt, *Sb, *P;
    float* Yp;
    cudaGetSymbolAddress((void**)&xT, g_xT);
    cudaGetSymbolAddress((void**)&Wk, g_Wk);
    cudaGetSymbolAddress((void**)&Wq, g_Wq);
    cudaGetSymbolAddress((void**)&Wv, g_Wv);
    cudaGetSymbolAddress((void**)&Wo, g_Wo);
    cudaGetSymbolAddress((void**)&Kt, g_Kt);
    cudaGetSymbolAddress((void**)&Qt, g_Qt);
    cudaGetSymbolAddress((void**)&Vt, g_Vt);
    cudaGetSymbolAddress((void**)&V,  g_V);
    cudaGetSymbolAddress((void**)&Yt, g_Yt);
    cudaGetSymbolAddress((void**)&Sb, g_Sb);
    cudaGetSymbolAddress((void**)&P,  g_P);
    cudaGetSymbolAddress((void**)&Yp, g_Yp);

    cudaFuncSetAttribute(tgemm<0>, cudaFuncAttributeMaxDynamicSharedMemorySize, SMEMSZ);
    cudaFuncSetAttribute(tgemm<1>, cudaFuncAttributeMaxDynamicSharedMemorySize, SMEMSZ);
    cudaFuncSetAttribute(tgemm<4>, cudaFuncAttributeMaxDynamicSharedMemorySize, SMEMSZ);
    cudaFuncSetAttribute(tgemm<5>, cudaFuncAttributeMaxDynamicSharedMemorySize, SMEMSZ);

    const size_t pstr = (size_t)NDIM * CIDIM;   // Kt/Qt/Vt/Yt batch stride
    const size_t vstr = (size_t)CIDIM * NDIM;   // V batch stride
    const size_t xstr = (size_t)CDIM * NDIM;    // x/out batch stride
    const size_t tstr = (size_t)NDIM * CDIM;    // xT batch stride
    const size_t sstr = (size_t)NDIM * NDIM;    // Sb/P batch stride
    const size_t khStr = (size_t)BSZ * pstr;    // split-K partial stride
    float* Y0 = Yp;
    float* Y1 = Yp + khStr;

    const int w4 = (CIDIM * CDIM) / 4;

    // 0) converts (single launch for weights, one for xT)
    transpose_cvt<<<dim3(NDIM / 32, CDIM / 32, BSZ), dim3(32, 8)>>>(x, xT);
    cvt_weights<<<dim3((w4 + 255) / 256, 4), 256>>>(Wkf, Wqf, Wvf, Wof,
                                                    Wk, Wq, Wv, Wo, w4);

    // 1) K, Q, V projections merged (TRIPLE): {Kt,Qt,Vt}[n,d] = xT[n,:]·W[d,:] + b[d]
    tgemm<1><<<dim3(CIDIM / 128, NDIM / 128, 3 * BSZ), 128, SMEMSZ>>>(
        xT, Wk, Wq, Wv,
        nullptr, Kt, Qt, Vt,
        CDIM, CDIM, CIDIM, tstr, 0, pstr, 0, bk, bq, bv, nullptr, 0, 1.0f);

    // 1b) V[c,n] = transpose(Vt)
    transpose_v<<<dim3(NDIM / 32, CIDIM / 32, BSZ), dim3(32, 8)>>>(Vt, V);

    // 2) Sb[i,j] = bf16( (1/T) Kt[i,:]·Qt[j,:] )
    tgemm<0><<<dim3(NDIM / 128, NDIM / 128, BSZ), 128, SMEMSZ>>>(
        Kt, Qt, nullptr, nullptr,
        nullptr, Sb, nullptr, nullptr,
        CIDIM, CIDIM, NDIM, pstr, pstr, sstr, 0, nullptr, nullptr, nullptr,
        nullptr, 0, 1.0f / (float)TDIM);

    // 3) softmax -> P bf16
    softmax_cvt<<<BSZ * NDIM, 256>>>(Sb, P, NDIM);

    // 4) Y partials: Yp[kh][i,c] = sum_{j in half kh} P[i,j]·V[c,j]  (split-K x2)
    tgemm<5><<<dim3(CIDIM / 128, NDIM / 128, 2 * BSZ), 128, SMEMSZ>>>(
        P, V, nullptr, nullptr,
        Y0, nullptr, nullptr, nullptr,
        NHALF, NDIM, CIDIM, sstr, vstr, pstr, khStr,
        nullptr, nullptr, nullptr, nullptr, 0, 1.0f);

    // 4b) Yt = bf16(Y0 + Y1)
    {
        const int n4 = (int)((size_t)BSZ * NDIM * CIDIM / 4);
        combine_cvt<<<(n4 + 255) / 256, 256>>>(Y0, Y1, Yt, n4);
    }

    // 5) out[c,n] = Wo[c,:]·Yt[n,:] + bo[c] + x[c,n]  (fp32 out)
    tgemm<4><<<dim3(NDIM / 128, CDIM / 128, BSZ), 128, SMEMSZ>>>(
        Wo, Yt, nullptr, nullptr,
        out, nullptr, nullptr, nullptr,
        CIDIM, CIDIM, NDIM, 0, pstr, xstr, 0, bo, nullptr, nullptr, x, xstr, 1.0f);
}

// round 16
// speedup vs baseline: 1.0876x; 1.0105x over previous
#include <cuda_runtime.h>
#include <cuda_bf16.h>
#include <cstdint>

// Problem constants
#define BSZ   2
#define CDIM  1024
#define CIDIM 512
#define NDIM  6272     // 32*14*14 = 49*128
#define NHALF 3136     // NDIM/2 (split-K for alpha*V)
#define TDIM  32

// bf16 scratch (allocation-free rule: __device__ globals)
__device__ __align__(256) __nv_bfloat16 g_xT[(size_t)BSZ * NDIM * CDIM];
__device__ __align__(256) __nv_bfloat16 g_Wk[CIDIM * CDIM];
__device__ __align__(256) __nv_bfloat16 g_Wq[CIDIM * CDIM];
__device__ __align__(256) __nv_bfloat16 g_Wv[CIDIM * CDIM];
__device__ __align__(256) __nv_bfloat16 g_Wo[CDIM * CIDIM];
__device__ __align__(256) __nv_bfloat16 g_Kt[(size_t)BSZ * NDIM * CIDIM];
__device__ __align__(256) __nv_bfloat16 g_Qt[(size_t)BSZ * NDIM * CIDIM];
__device__ __align__(256) __nv_bfloat16 g_V [(size_t)BSZ * CIDIM * NDIM]; // V [c,n]
__device__ __align__(256) __nv_bfloat16 g_Yt[(size_t)BSZ * NDIM * CIDIM];
__device__ __align__(256) __nv_bfloat16 g_Sb[(size_t)BSZ * NDIM * NDIM]; // bf16 scores
__device__ __align__(256) __nv_bfloat16 g_P [(size_t)BSZ * NDIM * NDIM]; // bf16 probs
__device__ __align__(256) float         g_Yp[(size_t)2 * BSZ * NDIM * CIDIM]; // split-K partials

// ---------------------------------------------------------------------------
__device__ __forceinline__ uint32_t smem_u32(const void* p) {
    uint32_t a;
    asm("{ .reg .u64 t; cvta.to.shared.u64 t, %1; cvt.u32.u64 %0, t; }"
        : "=r"(a) : "l"(p));
    return a;
}

#define LDSM4(rr, addr) \
    asm volatile("ldmatrix.sync.aligned.m8n8.x4.shared.b16 {%0,%1,%2,%3}, [%4];" \
        : "=r"((rr)[0]), "=r"((rr)[1]), "=r"((rr)[2]), "=r"((rr)[3]) : "r"(addr))

#define MMA(dd, aa, b0v, b1v) \
    asm volatile("mma.sync.aligned.m16n8k16.row.col.f32.bf16.bf16.f32 " \
        "{%0,%1,%2,%3}, {%4,%5,%6,%7}, {%8,%9}, {%0,%1,%2,%3};" \
        : "+f"((dd)[0]), "+f"((dd)[1]), "+f"((dd)[2]), "+f"((dd)[3]) \
        : "r"((aa)[0]), "r"((aa)[1]), "r"((aa)[2]), "r"((aa)[3]), \
          "r"(b0v), "r"(b1v))

#define CP16(dst, src) \
    asm volatile("cp.async.cg.shared.global [%0], [%1], 16;" :: "r"(dst), "l"(src))
#define CP_COMMIT() asm volatile("cp.async.commit_group;" ::: "memory")
#define CP_WAIT0()  asm volatile("cp.async.wait_group 0;" ::: "memory")

// SMEM: per stage 2 tiles (A, B), each 128 rows x 144B (128B data + 16 pad)
// K-chunk = 64 elements (128 bytes).
#define ROWB   144u
#define TILEB  (128u * ROWB)     // 18432
#define STAGEB (2u * TILEB)      // 36864
#define SMEMSZ (2u * STAGEB)     // 73728

// Transposed V staging tile: 128 x 136 shorts (272 B pitch, 16B-aligned rows)
#define VPITCH 136u

__device__ __forceinline__ uint32_t cvt2(float a, float b) {
    __nv_bfloat16 ha = __float2bfloat16(a);
    __nv_bfloat16 hb = __float2bfloat16(b);
    return (uint32_t)__bfloat16_as_ushort(ha)
         | ((uint32_t)__bfloat16_as_ushort(hb) << 16);
}
__device__ __forceinline__ void unpack2(uint32_t u, float& a, float& b) {
    a = __bfloat162float(__ushort_as_bfloat16((unsigned short)(u & 0xffff)));
    b = __bfloat162float(__ushort_as_bfloat16((unsigned short)(u >> 16)));
}
__device__ __forceinline__ unsigned short cvt1(float a) {
    return __bfloat16_as_ushort(__float2bfloat16(a));
}

// ---------------------------------------------------------------------------
// Pure-bf16 GEMM: acc[i,j] = sum_k A[i,k]*B[j,k]   (fp32 accumulate)
// A: M x K (K-major, ld=ldab), B: N' x K (K-major, ld=ldab)
// CTA tile 128x128, 128 threads, 4 warps (2x2), warp tile 64x64, K-chunk 64.
// EPI: 0 = bf16 out, scale                (scores; z = batch)
//      1 = TRIPLE bf16 out + bias[col]    (KQV proj; z = batch + 2*sel, sel 0..2;
//                                          sel==2 writes TRANSPOSED via smem -> C2=V[c,n])
//      4 = f32 out + bias[row] + resid    (out proj; z = batch)
//      5 = split-K f32 partial out        (alphaV; z = batch + 2*kh, kh 0..1)
// ---------------------------------------------------------------------------
template <int EPI>
__global__ __launch_bounds__(128, 2)
void tgemm(const __nv_bfloat16* __restrict__ Ab,
           const __nv_bfloat16* __restrict__ B0, const __nv_bfloat16* __restrict__ B1,
           const __nv_bfloat16* __restrict__ B2,
           float* __restrict__ Cf,
           __nv_bfloat16* __restrict__ C0, __nv_bfloat16* __restrict__ C1,
           __nv_bfloat16* __restrict__ C2,
           int Kd, int ldab, int ldc,
           size_t aStr, size_t bStr, size_t cStr, size_t khStr,
           const float* __restrict__ bias0, const float* __restrict__ bias1,
           const float* __restrict__ bias2,
           const float* __restrict__ resid, size_t rStr, float scale)
{
    extern __shared__ __align__(128) char smem[];
    const int tid  = threadIdx.x;
    const int lane = tid & 31;
    const int wid  = tid >> 5;        // 0..3
    const int wm   = wid >> 1;        // 0..1
    const int wn   = wid & 1;         // 0..1

    const int batch = blockIdx.z & 1;
    const int sel   = blockIdx.z >> 1;

    const __nv_bfloat16* Ap = Ab + (size_t)batch * aStr;
    const __nv_bfloat16* Bp;
    if (EPI == 1) Bp = (sel == 0) ? B0 : (sel == 1) ? B1 : B2;
    else          Bp = B0;
    Bp += (size_t)batch * bStr;
    if (EPI == 5) {
        const int koff = sel * NHALF;
        Ap += koff; Bp += koff;
    }

    const int rowA = blockIdx.y * 128;
    const int rowB = blockIdx.x * 128;
    const uint32_t sb = smem_u32(smem);

    // ldmatrix base addresses
    const uint32_t aAddr = sb
        + (uint32_t)(wm * 64 + (lane & 15)) * ROWB + (uint32_t)(lane >> 4) * 16;
    const int bq = lane >> 3;
    const uint32_t bAddr = sb + TILEB
        + (uint32_t)(wn * 64 + (bq >> 1) * 8 + (lane & 7)) * ROWB
        + (uint32_t)(bq & 1) * 16;

    float d[4][8][4];
    #pragma unroll
    for (int i = 0; i < 4; i++)
        #pragma unroll
        for (int j = 0; j < 8; j++)
            #pragma unroll
            for (int q = 0; q < 4; q++) d[i][j][q] = 0.f;

    const int nk = Kd / 64;
    const int lrow = tid >> 3;        // 0..15
    const int lc8  = (tid & 7) * 8;   // 0..56 (elements; x2 = byte offset)

    auto LOAD = [&](int kc, int s) {
        const uint32_t so = sb + (uint32_t)s * STAGEB;
        const int k0 = kc * 64 + lc8;
        #pragma unroll
        for (int t = 0; t < 2; t++) {
            const __nv_bfloat16* src = t ? Bp : Ap;
            const int rb = t ? rowB : rowA;
            #pragma unroll
            for (int r = 0; r < 8; r++) {
                const int row = lrow + r * 16;
                const uint32_t dst = so + (uint32_t)t * TILEB
                                   + (uint32_t)row * ROWB + (uint32_t)(lc8 * 2);
                CP16(dst, src + (size_t)(rb + row) * ldab + k0);
            }
        }
        CP_COMMIT();
    };

    // B fragments resident (64 cols), A streamed per mi; 8 MMA per A-LDSM.
    auto COMPUTE = [&](int s) {
        const uint32_t so = (uint32_t)s * STAGEB;
        #pragma unroll
        for (int ks = 0; ks < 4; ks++) {
            const uint32_t ab = aAddr + so + ks * 32;
            const uint32_t bb = bAddr + so + ks * 32;
            uint32_t bh[4][4];
            #pragma unroll
            for (int np = 0; np < 4; np++)
                LDSM4(bh[np], bb + np * 16 * ROWB);
            #pragma unroll
            for (int mi = 0; mi < 4; mi++) {
                uint32_t ah[4];
                LDSM4(ah, ab + mi * 16 * ROWB);
                #pragma unroll
                for (int ni = 0; ni < 8; ni++) {
                    const int np = ni >> 1, h = (ni & 1) * 2;
                    MMA(d[mi][ni], ah, bh[np][h], bh[np][h + 1]);
                }
            }
        }
    };

    LOAD(0, 0);
    for (int c = 0; c < nk; c++) {
        const int s = c & 1;
        CP_WAIT0();
        __syncthreads();
        if (c + 1 < nk) LOAD(c + 1, s ^ 1);
        COMPUTE(s);
    }

    // ---- epilogue ----
    const int r0base = rowA + wm * 64;
    const int c0base = rowB + wn * 64;

    // V slice of the TRIPLE projection: stage transposed tile in smem,
    // then write V[c, n] coalesced. (Arithmetic identical to the row-major path.)
    if (EPI == 1 && sel == 2) {
        __syncthreads();   // all warps done with pipeline smem
        ushort* vs = (ushort*)smem;      // [128 c][VPITCH] with n contiguous
        const float* bp2 = bias2;
        #pragma unroll
        for (int mi = 0; mi < 4; mi++) {
            const int n0l = (wm * 64 + mi * 16 + (lane >> 2)) ;   // local n
            const int n1l = n0l + 8;
            #pragma unroll
            for (int ni = 0; ni < 8; ni++) {
                const int cl = wn * 64 + ni * 8 + (lane & 3) * 2; // local c
                const float b0 = bp2[rowB + cl], b1 = bp2[rowB + cl + 1];
                vs[(uint32_t)cl * VPITCH + n0l]       = cvt1(d[mi][ni][0] + b0);
                vs[(uint32_t)(cl + 1) * VPITCH + n0l] = cvt1(d[mi][ni][1] + b1);
                vs[(uint32_t)cl * VPITCH + n1l]       = cvt1(d[mi][ni][2] + b0);
                vs[(uint32_t)(cl + 1) * VPITCH + n1l] = cvt1(d[mi][ni][3] + b1);
            }
        }
        __syncthreads();
        __nv_bfloat16* Vg = C2 + (size_t)batch * ((size_t)CIDIM * NDIM);
        // 128 rows x 16 uint4 chunks = 2048 chunks; 128 threads -> 16 iters
        #pragma unroll
        for (int it = 0; it < 16; it++) {
            const int u  = it * 128 + tid;
            const int cl = u >> 4;
            const int o8 = (u & 15) * 8;          // element offset within row
            uint4 val = *(const uint4*)(vs + (uint32_t)cl * VPITCH + o8);
            *(uint4*)(Vg + (size_t)(rowB + cl) * NDIM + rowA + o8) = val;
        }
        return;
    }

    float* Cfp = nullptr;
    __nv_bfloat16* Cb = nullptr;
    if (EPI == 4) Cfp = Cf + (size_t)batch * cStr;
    if (EPI == 5) Cfp = Cf + (size_t)batch * cStr + (size_t)sel * khStr;
    if (EPI == 0) Cb = C0 + (size_t)batch * cStr;
    if (EPI == 1)
        Cb = ((sel == 0) ? C0 : C1) + (size_t)batch * cStr;
    const float* bp = (EPI == 1)
        ? ((sel == 0) ? bias0 : bias1) : bias0;

    #pragma unroll
    for (int mi = 0; mi < 4; mi++) {
        const int row0 = r0base + mi * 16 + (lane >> 2);
        const int row1 = row0 + 8;
        float bi0 = 0.f, bi1 = 0.f;
        if (EPI == 4) { bi0 = bp[row0]; bi1 = bp[row1]; }
        #pragma unroll
        for (int ni = 0; ni < 8; ni++) {
            const int col = c0base + ni * 8 + (lane & 3) * 2;
            float v00 = d[mi][ni][0] * scale, v01 = d[mi][ni][1] * scale;
            float v10 = d[mi][ni][2] * scale, v11 = d[mi][ni][3] * scale;
            if (EPI == 1) {
                float b0 = bp[col], b1 = bp[col + 1];
                v00 += b0; v01 += b1; v10 += b0; v11 += b1;
            }
            if (EPI == 4) {
                v00 += bi0; v01 += bi0; v10 += bi1; v11 += bi1;
                const float* rb = resid + (size_t)batch * rStr;
                float2 q0 = *(const float2*)(rb + (size_t)row0 * ldc + col);
                float2 q1 = *(const float2*)(rb + (size_t)row1 * ldc + col);
                v00 += q0.x; v01 += q0.y; v10 += q1.x; v11 += q1.y;
            }
            if (EPI == 4 || EPI == 5) {
                *(float2*)(Cfp + (size_t)row0 * ldc + col) = make_float2(v00, v01);
                *(float2*)(Cfp + (size_t)row1 * ldc + col) = make_float2(v10, v11);
            } else {
                *(uint32_t*)(Cb + (size_t)row0 * ldc + col) = cvt2(v00, v01);
                *(uint32_t*)(Cb + (size_t)row1 * ldc + col) = cvt2(v10, v11);
            }
        }
    }
}

// ---------------------------------------------------------------------------
// 32x32 tiled transpose + convert: x (B,C,N) fp32 -> xT (B,N,C) bf16
// ---------------------------------------------------------------------------
__global__ __launch_bounds__(256)
void transpose_cvt(const float* __restrict__ src, __nv_bfloat16* __restrict__ dst)
{
    __shared__ float t[32][33];
    const float* s = src + (size_t)blockIdx.z * CDIM * NDIM;
    __nv_bfloat16* o = dst + (size_t)blockIdx.z * NDIM * CDIM;
    const int n0 = blockIdx.x * 32;
    const int c0 = blockIdx.y * 32;
    const int tx = threadIdx.x, ty = threadIdx.y;
    #pragma unroll
    for (int r = 0; r < 4; r++)
        t[ty + r * 8][tx] = s[(size_t)(c0 + ty + r * 8) * NDIM + n0 + tx];
    __syncthreads();
    #pragma unroll
    for (int r = 0; r < 4; r++)
        o[(size_t)(n0 + ty + r * 8) * CDIM + c0 + tx] =
            __float2bfloat16(t[tx][ty + r * 8]);
}

// All 4 weight matrices fp32 -> bf16 in one launch (blockIdx.y selects matrix).
__global__ __launch_bounds__(256)
void cvt_weights(const float* __restrict__ s0, const float* __restrict__ s1,
                 const float* __restrict__ s2, const float* __restrict__ s3,
                 __nv_bfloat16* __restrict__ d0, __nv_bfloat16* __restrict__ d1,
                 __nv_bfloat16* __restrict__ d2, __nv_bfloat16* __restrict__ d3,
                 int n4)
{
    const int m = blockIdx.y;
    const float* src = (m == 0) ? s0 : (m == 1) ? s1 : (m == 2) ? s2 : s3;
    __nv_bfloat16* dst = (m == 0) ? d0 : (m == 1) ? d1 : (m == 2) ? d2 : d3;
    const int i = blockIdx.x * 256 + threadIdx.x;
    if (i >= n4) return;
    float4 v = ((const float4*)src)[i];
    ((uint2*)dst)[i] = make_uint2(cvt2(v.x, v.y), cvt2(v.z, v.w));
}

// Combine split-K partials (y0 + y1) -> bf16
__global__ __launch_bounds__(256)
void combine_cvt(const float* __restrict__ y0, const float* __restrict__ y1,
                 __nv_bfloat16* __restrict__ dst, int n4)
{
    const int i = blockIdx.x * 256 + threadIdx.x;
    if (i >= n4) return;
    float4 a = ((const float4*)y0)[i];
    float4 b = ((const float4*)y1)[i];
    ((uint2*)dst)[i] = make_uint2(cvt2(a.x + b.x, a.y + b.y),
                                  cvt2(a.z + b.z, a.w + b.w));
}

// ---------------------------------------------------------------------------
// Row softmax: bf16 scores in -> bf16 probabilities out, vectorized uint4
// (8 bf16 per ld/st). Row length 6272 = 784 uint4; 256 threads, 4 iters.
// ---------------------------------------------------------------------------
#define SM_V4 4   // uint4 per thread (4*256 = 1024 >= 784)
__global__ __launch_bounds__(256)
void softmax_cvt(const __nv_bfloat16* __restrict__ S, __nv_bfloat16* __restrict__ P,
                 int n)
{
    const uint4* row = (const uint4*)(S + (size_t)blockIdx.x * n);
    uint4* pr = (uint4*)(P + (size_t)blockIdx.x * n);
    const int n4 = n / 8;                 // 784
    const int t = threadIdx.x;
    __shared__ float red[256];

    float vals[SM_V4 * 8];
    float mx = -3.402823466e38f;
    #pragma unroll
    for (int v = 0; v < SM_V4; v++) {
        const int j = v * 256 + t;
        if (j < n4) {
            uint4 u = row[j];
            float* p = vals + v * 8;
            unpack2(u.x, p[0], p[1]); unpack2(u.y, p[2], p[3]);
            unpack2(u.z, p[4], p[5]); unpack2(u.w, p[6], p[7]);
            #pragma unroll
            for (int e = 0; e < 8; e++) mx = fmaxf(mx, p[e]);
        }
    }
    red[t] = mx; __syncthreads();
    for (int s = 128; s > 0; s >>= 1) {
        if (t < s) red[t] = fmaxf(red[t], red[t + s]);
        __syncthreads();
    }
    mx = red[0];
    __syncthreads();

    float sum = 0.f;
    #pragma unroll
    for (int v = 0; v < SM_V4; v++) {
        const int j = v * 256 + t;
        if (j < n4) {
            float* p = vals + v * 8;
            #pragma unroll
            for (int e = 0; e < 8; e++) { p[e] = __expf(p[e] - mx); sum += p[e]; }
        }
    }
    red[t] = sum; __syncthreads();
    for (int s = 128; s > 0; s >>= 1) {
        if (t < s) red[t] += red[t + s];
        __syncthreads();
    }
    const float inv = 1.f / red[0];

    #pragma unroll
    for (int v = 0; v < SM_V4; v++) {
        const int j = v * 256 + t;
        if (j < n4) {
            float* p = vals + v * 8;
            uint4 u;
            u.x = cvt2(p[0] * inv, p[1] * inv);
            u.y = cvt2(p[2] * inv, p[3] * inv);
            u.z = cvt2(p[4] * inv, p[5] * inv);
            u.w = cvt2(p[6] * inv, p[7] * inv);
            pr[j] = u;
        }
    }
}

// ---------------------------------------------------------------------------
extern "C" void kernel_launch(void* const* d_in, const int* in_sizes, int n_in,
                              void* d_out, int out_size)
{
    const float* x   = (const float*)d_in[0];   // (B, C, N)
    const float* Wkf = (const float*)d_in[1];   // (CI, C)
    const float* bk  = (const float*)d_in[2];
    const float* Wqf = (const float*)d_in[3];
    const float* bq  = (const float*)d_in[4];
    const float* Wvf = (const float*)d_in[5];
    const float* bv  = (const float*)d_in[6];
    const float* Wof = (const float*)d_in[7];   // (C, CI)
    const float* bo  = (const float*)d_in[8];
    float* out = (float*)d_out;                 // (B, C, N)

    __nv_bfloat16 *xT, *Wk, *Wq, *Wv, *Wo, *Kt, *Qt, *V, *Yt, *Sb, *P;
    float* Yp;
    cudaGetSymbolAddress((void**)&xT, g_xT);
    cudaGetSymbolAddress((void**)&Wk, g_Wk);
    cudaGetSymbolAddress((void**)&Wq, g_Wq);
    cudaGetSymbolAddress((void**)&Wv, g_Wv);
    cudaGetSymbolAddress((void**)&Wo, g_Wo);
    cudaGetSymbolAddress((void**)&Kt, g_Kt);
    cudaGetSymbolAddress((void**)&Qt, g_Qt);
    cudaGetSymbolAddress((void**)&V,  g_V);
    cudaGetSymbolAddress((void**)&Yt, g_Yt);
    cudaGetSymbolAddress((void**)&Sb, g_Sb);
    cudaGetSymbolAddress((void**)&P,  g_P);
    cudaGetSymbolAddress((void**)&Yp, g_Yp);

    cudaFuncSetAttribute(tgemm<0>, cudaFuncAttributeMaxDynamicSharedMemorySize, SMEMSZ);
    cudaFuncSetAttribute(tgemm<1>, cudaFuncAttributeMaxDynamicSharedMemorySize, SMEMSZ);
    cudaFuncSetAttribute(tgemm<4>, cudaFuncAttributeMaxDynamicSharedMemorySize, SMEMSZ);
    cudaFuncSetAttribute(tgemm<5>, cudaFuncAttributeMaxDynamicSharedMemorySize, SMEMSZ);

    const size_t pstr = (size_t)NDIM * CIDIM;   // Kt/Qt/Yt batch stride
    const size_t vstr = (size_t)CIDIM * NDIM;   // V batch stride
    const size_t xstr = (size_t)CDIM * NDIM;    // x/out batch stride
    const size_t tstr = (size_t)NDIM * CDIM;    // xT batch stride
    const size_t sstr = (size_t)NDIM * NDIM;    // Sb/P batch stride
    const size_t khStr = (size_t)BSZ * pstr;    // split-K partial stride
    float* Y0 = Yp;
    float* Y1 = Yp + khStr;

    const int w4 = (CIDIM * CDIM) / 4;

    // 0) converts (single launch for weights, one for xT)
    transpose_cvt<<<dim3(NDIM / 32, CDIM / 32, BSZ), dim3(32, 8)>>>(x, xT);
    cvt_weights<<<dim3((w4 + 255) / 256, 4), 256>>>(Wkf, Wqf, Wvf, Wof,
                                                    Wk, Wq, Wv, Wo, w4);

    // 1) K, Q, V projections merged (TRIPLE): Kt/Qt row-major; V written
    //    TRANSPOSED directly as V[c,n] from the sel==2 epilogue.
    tgemm<1><<<dim3(CIDIM / 128, NDIM / 128, 3 * BSZ), 128, SMEMSZ>>>(
        xT, Wk, Wq, Wv,
        nullptr, Kt, Qt, V,
        CDIM, CDIM, CIDIM, tstr, 0, pstr, 0, bk, bq, bv, nullptr, 0, 1.0f);

    // 2) Sb[i,j] = bf16( (1/T) Kt[i,:]·Qt[j,:] )
    tgemm<0><<<dim3(NDIM / 128, NDIM / 128, BSZ), 128, SMEMSZ>>>(
        Kt, Qt, nullptr, nullptr,
        nullptr, Sb, nullptr, nullptr,
        CIDIM, CIDIM, NDIM, pstr, pstr, sstr, 0, nullptr, nullptr, nullptr,
        nullptr, 0, 1.0f / (float)TDIM);

    // 3) softmax -> P bf16
    softmax_cvt<<<BSZ * NDIM, 256>>>(Sb, P, NDIM);

    // 4) Y partials: Yp[kh][i,c] = sum_{j in half kh} P[i,j]·V[c,j]  (split-K x2)
    tgemm<5><<<dim3(CIDIM / 128, NDIM / 128, 2 * BSZ), 128, SMEMSZ>>>(
        P, V, nullptr, nullptr,
        Y0, nullptr, nullptr, nullptr,
        NHALF, NDIM, CIDIM, sstr, vstr, pstr, khStr,
        nullptr, nullptr, nullptr, nullptr, 0, 1.0f);

    // 4b) Yt = bf16(Y0 + Y1)
    {
        const int n4 = (int)((size_t)BSZ * NDIM * CIDIM / 4);
        combine_cvt<<<(n4 + 255) / 256, 256>>>(Y0, Y1, Yt, n4);
    }

    // 5) out[c,n] = Wo[c,:]·Yt[n,:] + bo[c] + x[c,n]  (fp32 out)
    tgemm<4><<<dim3(NDIM / 128, CDIM / 128, BSZ), 128, SMEMSZ>>>(
        Wo, Yt, nullptr, nullptr,
        out, nullptr, nullptr, nullptr,
        CIDIM, CIDIM, NDIM, 0, pstr, xstr, 0, bo, nullptr, nullptr, x, xstr, 1.0f);
}